// round 16
// baseline (speedup 1.0000x reference)
#include <cuda_runtime.h>
#include <cuda_bf16.h>
#include <mma.h>
#include <math.h>
#include <cstdint>

using namespace nvcuda;
typedef __nv_bfloat16 bf16;

#define LN_EPS 1e-5f

// persistent scratch (device globals: allocation-free)
__device__ float g_xres[(size_t)200704 * 192];        // mid residual
__device__ bf16  g_qkv [(size_t)200704 * 576];        // LN1 @ Wqkv^T + b
__device__ bf16  g_attno[(size_t)200704 * 192];       // attention output (pre-proj)
__device__ bf16  g_wqkv[576 * 192];
__device__ bf16  g_wproj[192 * 192];
__device__ bf16  g_wfc1[768 * 192];
__device__ bf16  g_wfc2[192 * 768];

typedef wmma::fragment<wmma::matrix_a, 16, 16, 16, bf16, wmma::row_major> FA;
typedef wmma::fragment<wmma::matrix_b, 16, 16, 16, bf16, wmma::col_major> FBc;
typedef wmma::fragment<wmma::matrix_b, 16, 16, 16, bf16, wmma::row_major> FBr;
typedef wmma::fragment<wmma::accumulator, 16, 16, 16, float> FC;

// ---------------------------------------------------------------------------
__device__ __forceinline__ void cpa16(void* smem_dst, const void* gsrc) {
    unsigned int a = (unsigned int)__cvta_generic_to_shared(smem_dst);
    asm volatile("cp.async.cg.shared.global [%0], [%1], 16;\n" :: "r"(a), "l"(gsrc));
}
#define CP_COMMIT() asm volatile("cp.async.commit_group;\n" ::: "memory")
#define CP_WAIT0()  asm volatile("cp.async.wait_group 0;\n" ::: "memory")

// ---------------------------------------------------------------------------
__global__ void cvt_all(const float* __restrict__ wqkv, const float* __restrict__ wproj,
                        const float* __restrict__ wfc1, const float* __restrict__ wfc2)
{
    int i = blockIdx.x * 256 + threadIdx.x;
    if (i < 110592) g_wqkv[i]  = __float2bfloat16(wqkv[i]);
    if (i < 36864)  g_wproj[i] = __float2bfloat16(wproj[i]);
    if (i < 147456) {
        g_wfc1[i] = __float2bfloat16(wfc1[i]);
        g_wfc2[i] = __float2bfloat16(wfc2[i]);
    }
}

// ---------------------------------------------------------------------------
// shared helpers
// ---------------------------------------------------------------------------
#define G192_SM (51200 + 2 * 19968 + 13312)

template <int NTHREADS>
__device__ __forceinline__ void stage_A_ln_t(bf16* As, const float* __restrict__ xr,
                                             const float* __restrict__ g,
                                             const float* __restrict__ b,
                                             int wid, int lane)
{
    for (int r = wid; r < 128; r += NTHREADS / 32) {
        float v[6]; float s = 0.f;
#pragma unroll
        for (int j = 0; j < 6; j++) { v[j] = xr[r * 192 + j * 32 + lane]; s += v[j]; }
#pragma unroll
        for (int o = 16; o; o >>= 1) s += __shfl_xor_sync(0xffffffffu, s, o);
        float mu = s * (1.f / 192.f);
        float va = 0.f;
#pragma unroll
        for (int j = 0; j < 6; j++) { float d = v[j] - mu; va += d * d; }
#pragma unroll
        for (int o = 16; o; o >>= 1) va += __shfl_xor_sync(0xffffffffu, va, o);
        float rstd = rsqrtf(va * (1.f / 192.f) + LN_EPS);
#pragma unroll
        for (int j = 0; j < 6; j++) {
            int c = j * 32 + lane;
            As[r * 200 + c] = __float2bfloat16((v[j] - mu) * rstd * g[c] + b[c]);
        }
    }
}

// async-copy one 96x96 B tile (256-thread)
__device__ __forceinline__ void copy_B_tile(bf16* Bs, const bf16* __restrict__ W,
                                            int ldw, int n0, int k0, int tid)
{
    const bf16* src = W + (size_t)n0 * ldw + k0;
    for (int idx = tid; idx < 96 * 12; idx += 256) {
        int r = idx / 12, ch = (idx - r * 12) * 8;
        cpa16(Bs + r * 104 + ch, src + (size_t)r * ldw + ch);
    }
}

// generic async tile copy: ROWS x (CH16*8 cols), NTHREADS threads, dst ld LDD
template <int ROWS, int CH16, int NTHREADS, int LDD>
__device__ __forceinline__ void copy_tile(bf16* dst, const bf16* __restrict__ src,
                                          int lds, int tid)
{
    for (int idx = tid; idx < ROWS * CH16; idx += NTHREADS) {
        int r = idx / CH16, ch = (idx - r * CH16) * 8;
        cpa16(dst + r * LDD + ch, src + (size_t)r * lds + ch);
    }
}

// mma over one 96-K chunk (warp tile 32x48, B ld 104)
__device__ __forceinline__ void mma_chunk(const bf16* As, int ldA, int kbase,
                                          const bf16* Bs, int mt, int ng, FC acc[6])
{
#pragma unroll
    for (int kk = 0; kk < 96; kk += 16) {
        FA a0, a1;
        wmma::load_matrix_sync(a0, As + (mt * 32) * ldA + kbase + kk, ldA);
        wmma::load_matrix_sync(a1, As + (mt * 32 + 16) * ldA + kbase + kk, ldA);
#pragma unroll
        for (int j = 0; j < 3; j++) {
            FBc b;
            wmma::load_matrix_sync(b, Bs + (ng * 48 + j * 16) * 104 + kk, 104);
            wmma::mma_sync(acc[j],     a0, b, acc[j]);
            wmma::mma_sync(acc[j + 3], a1, b, acc[j + 3]);
        }
    }
}

// ---------------------------------------------------------------------------
// Per-warp barrier-free epilogue (qkv)
// ---------------------------------------------------------------------------
__device__ __forceinline__ void epi_frags_qkv(float* ws, FC acc[6], int mt, int ng,
                                              int cbase, int row0,
                                              const float* __restrict__ bias, int lane)
{
#pragma unroll
    for (int j = 0; j < 6; j++) {
        int r0 = row0 + mt * 32 + (j >= 3 ? 16 : 0);
        int c0 = cbase + ng * 48 + (j % 3) * 16;
        wmma::store_matrix_sync(ws, acc[j], 20, wmma::mem_row_major);
        __syncwarp();
        int rr = lane >> 1, cc = (lane & 1) * 8;
        const float* sp = ws + rr * 20 + cc;
        int gr = r0 + rr, gc = c0 + cc;
        uint4 u; bf16* pb = (bf16*)&u;
#pragma unroll
        for (int q = 0; q < 8; q++) pb[q] = __float2bfloat16(sp[q] + bias[gc + q]);
        *(uint4*)(g_qkv + (size_t)gr * 576 + gc) = u;
        __syncwarp();
    }
}

// ---------------------------------------------------------------------------
// Coalesced block-staged epilogue for proj: +b + x -> g_xres
// ---------------------------------------------------------------------------
__device__ __forceinline__ void epi_slice_proj(float* buf, FC acc[6], int mt, int ng,
                                               int cbase, int row0,
                                               const float* __restrict__ xin,
                                               const float* __restrict__ bias, int tid)
{
#pragma unroll
    for (int ph = 0; ph < 4; ph++) {
        const int h = ph >> 1, c = ph & 1;
        __syncthreads();
        if ((mt >> 1) == h && ng == c) {
            int lr = (mt & 1) * 32;
#pragma unroll
            for (int j = 0; j < 3; j++) {
                wmma::store_matrix_sync(buf + lr * 52 + j * 16,        acc[j],     52, wmma::mem_row_major);
                wmma::store_matrix_sync(buf + (lr + 16) * 52 + j * 16, acc[j + 3], 52, wmma::mem_row_major);
            }
        }
        __syncthreads();
        for (int idx = tid; idx < 64 * 48; idx += 256) {
            int r = idx / 48, cc = idx - r * 48;
            int gr = row0 + h * 64 + r;
            int gc = cbase + c * 48 + cc;
            size_t gi = (size_t)gr * 192 + gc;
            g_xres[gi] = buf[r * 52 + cc] + bias[gc] + xin[gi];
        }
    }
}

// ---------------------------------------------------------------------------
// Unified K=192 GEMM (qkv OP0, proj OP1): block 256, CTA = 128 rows,
// cp.async-pipelined 96x96 B tiles.
// ---------------------------------------------------------------------------
template <int NSLICES, int OP>
__global__ __launch_bounds__(256) void gemm192_kernel(
    const float* __restrict__ xin, const float* __restrict__ lng,
    const float* __restrict__ lnb, const float* __restrict__ bias)
{
    extern __shared__ char smc[];
    bf16*  As   = (bf16*)smc;
    bf16*  Bb0  = (bf16*)(smc + 51200);
    bf16*  Bb1  = (bf16*)(smc + 51200 + 19968);
    float* epi  = (float*)(smc + 51200 + 2 * 19968);

    const bf16* W = (OP == 0) ? g_wqkv : g_wproj;

    const int tid = threadIdx.x, wid = tid >> 5, lane = tid & 31;
    const int row0 = blockIdx.x * 128;
    const int mt = wid & 3, ng = wid >> 2;
    float* ws = epi + wid * 320;

    copy_B_tile(Bb0, W, 192, 0, 0, tid);
    if (OP == 1) {
        const bf16* src = g_attno + (size_t)row0 * 192;
        for (int idx = tid; idx < 128 * 24; idx += 256) {
            int r = idx / 24, ch = (idx - r * 24) * 8;
            cpa16(As + r * 200 + ch, src + (size_t)r * 192 + ch);
        }
    }
    CP_COMMIT();

    if (OP == 0) stage_A_ln_t<256>(As, xin + (size_t)row0 * 192, lng, lnb, wid, lane);

    FC acc[6];
#pragma unroll
    for (int j = 0; j < 6; j++) wmma::fill_fragment(acc[j], 0.f);

    const int T = NSLICES * 2;
    for (int t = 0; t < T; t++) {
        const int s = t >> 1, c = t & 1;
        bf16* Bcur = (t & 1) ? Bb1 : Bb0;
        bf16* Bnxt = (t & 1) ? Bb0 : Bb1;
        CP_WAIT0();
        __syncthreads();
        if (t + 1 < T) {
            copy_B_tile(Bnxt, W, 192, ((t + 1) >> 1) * 96, ((t + 1) & 1) * 96, tid);
            CP_COMMIT();
        }
        mma_chunk(As, 200, c * 96, Bcur, mt, ng, acc);
        if (c == 1) {
            if (OP == 1)
                epi_slice_proj(epi, acc, mt, ng, s * 96, row0, xin, bias, tid);
            else
                epi_frags_qkv(ws, acc, mt, ng, s * 96, row0, bias, lane);
#pragma unroll
            for (int j = 0; j < 6; j++) wmma::fill_fragment(acc[j], 0.f);
        }
    }
}

// ---------------------------------------------------------------------------
// FUSED MLP v2 — software-pipelined: fc1(p) and fc2(p-1) issued between the
// SAME pair of barriers (one __syncthreads per iteration), hid chunks of 64.
// block 512 (16 warps), CTA = 128 rows, 1 CTA/SM.
// smem: xn 51200 | W1b dbl 2x25600 | W2b dbl 2x27648 | hb dbl 2x18432 |
//       ws 20480  = 215040 B
// ---------------------------------------------------------------------------
#define MLP_XN   0
#define MLP_W1B  51200
#define MLP_W2B  (MLP_W1B + 2 * 25600)
#define MLP_HB   (MLP_W2B + 2 * 27648)
#define MLP_WS   (MLP_HB + 2 * 18432)
#define MLP_SM   (MLP_WS + 20480)

__global__ __launch_bounds__(512) void mlp_kernel(
    const float* __restrict__ ln2g, const float* __restrict__ ln2b,
    const float* __restrict__ bfc1, const float* __restrict__ bfc2,
    float* __restrict__ out)
{
    extern __shared__ char smc[];
    bf16*  xn  = (bf16*)(smc + MLP_XN);            // 128x200
    bf16*  W1b[2] = { (bf16*)(smc + MLP_W1B), (bf16*)(smc + MLP_W1B + 25600) };  // 64x200
    bf16*  W2b[2] = { (bf16*)(smc + MLP_W2B), (bf16*)(smc + MLP_W2B + 27648) };  // 192x72
    bf16*  hb[2]  = { (bf16*)(smc + MLP_HB),  (bf16*)(smc + MLP_HB + 18432) };   // 128x72
    float* wsb = (float*)(smc + MLP_WS);           // 16x320 f32 (also epi buf)

    const int tid = threadIdx.x, wid = tid >> 5, lane = tid & 31;
    const int row0 = blockIdx.x * 128;
    // fc1 tiling: warp = 16 rows x 32 cols (2 frags): rw = wid&7, cw = wid>>3
    const int rw = wid & 7, cw = wid >> 3;
    // fc2 tiling: warp = 32 rows x 48 cols (6 frags)
    const int mtf = wid & 3, ngf = wid >> 2;
    float* ws = wsb + wid * 320;

    // prologue: W1[0] in flight; LN2 -> xn
    copy_tile<64, 24, 512, 200>(W1b[0], g_wfc1, 192, tid);
    CP_COMMIT();
    stage_A_ln_t<512>(xn, g_xres + (size_t)row0 * 192, ln2g, ln2b, wid, lane);

    FC acc[6];
#pragma unroll
    for (int j = 0; j < 6; j++) wmma::fill_fragment(acc[j], 0.f);

    for (int p = 0; p <= 12; p++) {
        CP_WAIT0();
        __syncthreads();
        // 1-ahead prefetch (targets [(p+1)&1] / [p&1]; consumers read the other)
        if (p + 1 < 12)
            copy_tile<64, 24, 512, 200>(W1b[(p + 1) & 1],
                                        g_wfc1 + (size_t)(p + 1) * 64 * 192, 192, tid);
        if (p < 12)
            copy_tile<192, 8, 512, 72>(W2b[p & 1], g_wfc2 + (size_t)p * 64, 768, tid);
        CP_COMMIT();

        // fc1(p): h[128,64] = xn @ W1[p]^T  -> gelu -> hb[p&1]
        if (p < 12) {
            FC f[2];
#pragma unroll
            for (int j = 0; j < 2; j++) wmma::fill_fragment(f[j], 0.f);
#pragma unroll
            for (int k0 = 0; k0 < 192; k0 += 16) {
                FA a;
                wmma::load_matrix_sync(a, xn + (rw * 16) * 200 + k0, 200);
#pragma unroll
                for (int j = 0; j < 2; j++) {
                    FBc b;
                    wmma::load_matrix_sync(b, W1b[p & 1] + (cw * 32 + j * 16) * 200 + k0, 200);
                    wmma::mma_sync(f[j], a, b, f[j]);
                }
            }
#pragma unroll
            for (int j = 0; j < 2; j++) {
                wmma::store_matrix_sync(ws, f[j], 20, wmma::mem_row_major);
                __syncwarp();
                int rr = lane >> 1, cc = (lane & 1) * 8;
                const float* sp = ws + rr * 20 + cc;
                int lr = rw * 16 + rr;
                int lc = cw * 32 + j * 16 + cc;
                uint4 u; bf16* pb = (bf16*)&u;
#pragma unroll
                for (int q = 0; q < 8; q++) {
                    float v = sp[q] + bfc1[p * 64 + lc + q];
                    v = 0.5f * v * (1.f + erff(v * 0.70710678118654752f));
                    pb[q] = __float2bfloat16(v);
                }
                *(uint4*)(hb[p & 1] + lr * 72 + lc) = u;
                __syncwarp();
            }
        }

        // fc2(p-1): acc += hb[(p-1)&1] @ W2[p-1]^T  (K=64, ld 72)
        if (p >= 1) {
            const bf16* hA = hb[(p - 1) & 1];
            const bf16* Wc = W2b[(p - 1) & 1];
#pragma unroll
            for (int kk = 0; kk < 64; kk += 16) {
                FA a0, a1;
                wmma::load_matrix_sync(a0, hA + (mtf * 32) * 72 + kk, 72);
                wmma::load_matrix_sync(a1, hA + (mtf * 32 + 16) * 72 + kk, 72);
#pragma unroll
                for (int j = 0; j < 3; j++) {
                    FBc b;
                    wmma::load_matrix_sync(b, Wc + (ngf * 48 + j * 16) * 72 + kk, 72);
                    wmma::mma_sync(acc[j],     a0, b, acc[j]);
                    wmma::mma_sync(acc[j + 3], a1, b, acc[j + 3]);
                }
            }
        }
    }

    // epilogue: 8 phases (2 row-halves x 4 col-groups of 48), staged coalesced
    float* buf = wsb;   // 64x52 f32 = 13312 <= 20480
#pragma unroll
    for (int h = 0; h < 2; h++)
#pragma unroll
        for (int c = 0; c < 4; c++) {
            __syncthreads();
            if ((mtf >> 1) == h && ngf == c) {
                int lr = (mtf & 1) * 32;
#pragma unroll
                for (int j = 0; j < 3; j++) {
                    wmma::store_matrix_sync(buf + lr * 52 + j * 16,        acc[j],     52, wmma::mem_row_major);
                    wmma::store_matrix_sync(buf + (lr + 16) * 52 + j * 16, acc[j + 3], 52, wmma::mem_row_major);
                }
            }
            __syncthreads();
            for (int idx = tid; idx < 64 * 48; idx += 512) {
                int r = idx / 48, cc = idx - r * 48;
                int gr = row0 + h * 64 + r;
                int gc = c * 48 + cc;
                size_t gi = (size_t)gr * 192 + gc;
                out[gi] = buf[r * 52 + cc] + bfc2[gc] + g_xres[gi];
            }
        }
}

// ---------------------------------------------------------------------------
// attention core v2: ONE CTA PER WINDOW, 6 heads, cp.async double-buffered
// q/k/v head slices; mask as 64-bit bitmasks.  smem 57856 -> 3 CTAs/SM
// ---------------------------------------------------------------------------
#define AT_SM (2 * 15360 + 17408 + 9216 + 512)

__device__ __forceinline__ void stage_qkv_head(bf16* dst, size_t base, int h, int tid)
{
    for (int idx = tid; idx < 588; idx += 256) {
        int m = idx / 196, rem = idx - m * 196;
        int r = rem >> 2, c8 = (rem & 3) * 8;
        cpa16(dst + m * 2560 + r * 40 + c8,
              g_qkv + base + (size_t)r * 576 + m * 192 + h * 32 + c8);
    }
}

__global__ __launch_bounds__(256) void attn_core(const int* __restrict__ mask)
{
    extern __shared__ char smc[];
    bf16*  qkvb0 = (bf16*)smc;
    bf16*  qkvb1 = (bf16*)(smc + 15360);
    float* S     = (float*)(smc + 30720);
    bf16*  P     = (bf16*)(smc + 48128);
    unsigned long long* mb = (unsigned long long*)(smc + 57344);
    float* pvbuf = S;

    const int tid = threadIdx.x, wid = tid >> 5, lane = tid & 31;
    const int win = blockIdx.x;
    const size_t base = (size_t)(win * 49) * 576;

    {
        const int* mrow_base = mask + (size_t)win * 49 * 49;
        for (int r = wid; r < 49; r += 8) {
            const int* mrow = mrow_base + r * 49;
            unsigned m1 = __ballot_sync(0xffffffffu, mrow[lane] != 0);
            unsigned m2 = __ballot_sync(0xffffffffu,
                                        (lane + 32 < 49) ? (mrow[lane + 32] != 0) : 0);
            if (lane == 0) mb[r] = ((unsigned long long)m2 << 32) | m1;
        }
    }
    for (int idx = tid; idx < 150; idx += 256) {
        int b = idx / 75, e = idx - b * 75;
        int r = 49 + e / 5, c8 = (e % 5) * 8;
        bf16* vdst = (b ? qkvb1 : qkvb0) + 5120 + r * 40 + c8;
        uint4 z; z.x = z.y = z.z = z.w = 0u;
        *(uint4*)vdst = z;
    }

    stage_qkv_head(qkvb0, base, 0, tid);
    CP_COMMIT();
    __syncthreads();

    for (int h = 0; h < 6; h++) {
        bf16* cur = (h & 1) ? qkvb1 : qkvb0;
        bf16* nxt = (h & 1) ? qkvb0 : qkvb1;
        CP_WAIT0();
        __syncthreads();
        if (h + 1 < 6) {
            stage_qkv_head(nxt, base, h + 1, tid);
            CP_COMMIT();
        }
        bf16* qs = cur, *ks = cur + 2560, *vs = cur + 5120;

#pragma unroll
        for (int it = 0; it < 2; it++) {
            int t = wid + it * 8;
            int mt = t & 3, nt = t >> 2;
            FC c;
            wmma::fill_fragment(c, 0.f);
#pragma unroll
            for (int k0 = 0; k0 < 32; k0 += 16) {
                FA a;
                wmma::load_matrix_sync(a, qs + mt * 16 * 40 + k0, 40);
                FBc b;
                wmma::load_matrix_sync(b, ks + nt * 16 * 40 + k0, 40);
                wmma::mma_sync(c, a, b, c);
            }
            wmma::store_matrix_sync(S + mt * 16 * 68 + nt * 16, c, 68, wmma::mem_row_major);
        }
        __syncthreads();

        {
            const float scale = 0.17677669529663687f;
            for (int r = wid; r < 49; r += 8) {
                unsigned long long bits = mb[r];
                int j2 = lane + 32;
                bool m1 = (bits >> lane) & 1ull;
                bool m2 = (j2 < 49) && ((bits >> j2) & 1ull);
                float s1 = m1 ? S[r * 68 + lane] * scale : -1e30f;
                float s2 = m2 ? S[r * 68 + j2] * scale : -1e30f;
                float m = fmaxf(s1, s2);
#pragma unroll
                for (int o = 16; o; o >>= 1) m = fmaxf(m, __shfl_xor_sync(0xffffffffu, m, o));
                float e1 = __expf(s1 - m);
                float e2 = (j2 < 49) ? __expf(s2 - m) : 0.f;
                float sum = e1 + e2;
#pragma unroll
                for (int o = 16; o; o >>= 1) sum += __shfl_xor_sync(0xffffffffu, sum, o);
                float inv = 1.f / sum;
                P[r * 72 + lane] = __float2bfloat16(e1 * inv);
                P[r * 72 + j2]   = __float2bfloat16(e2 * inv);
            }
        }
        __syncthreads();

        {
            int mt = wid & 3, nt = wid >> 2;
            FC c;
            wmma::fill_fragment(c, 0.f);
#pragma unroll
            for (int k0 = 0; k0 < 64; k0 += 16) {
                FA a;
                wmma::load_matrix_sync(a, P + mt * 16 * 72 + k0, 72);
                FBr b;
                wmma::load_matrix_sync(b, vs + k0 * 40 + nt * 16, 40);
                wmma::mma_sync(c, a, b, c);
            }
            wmma::store_matrix_sync(pvbuf + mt * 16 * 40 + nt * 16, c, 40, wmma::mem_row_major);
        }
        __syncthreads();

        for (int idx = tid; idx < 49 * 32; idx += 256) {
            int r = idx >> 5, c = idx & 31;
            g_attno[(size_t)(win * 49 + r) * 192 + h * 32 + c] =
                __float2bfloat16(pvbuf[r * 40 + c]);
        }
        __syncthreads();
    }
}

// ---------------------------------------------------------------------------

extern "C" void kernel_launch(void* const* d_in, const int* in_sizes, int n_in,
                              void* d_out, int out_size)
{
    const float* x     = (const float*)d_in[0];
    const int*   msk   = (const int*)  d_in[1];
    const float* ln1g  = (const float*)d_in[2];
    const float* ln1b  = (const float*)d_in[3];
    const float* bqkv  = (const float*)d_in[5];
    const float* bproj = (const float*)d_in[7];
    const float* ln2g  = (const float*)d_in[8];
    const float* ln2b  = (const float*)d_in[9];
    const float* bfc1  = (const float*)d_in[11];
    const float* bfc2  = (const float*)d_in[13];
    float* out = (float*)d_out;

    cudaFuncSetAttribute(gemm192_kernel<6, 0>, cudaFuncAttributeMaxDynamicSharedMemorySize, G192_SM);
    cudaFuncSetAttribute(gemm192_kernel<2, 1>, cudaFuncAttributeMaxDynamicSharedMemorySize, G192_SM);
    cudaFuncSetAttribute(mlp_kernel, cudaFuncAttributeMaxDynamicSharedMemorySize, MLP_SM);
    cudaFuncSetAttribute(attn_core,  cudaFuncAttributeMaxDynamicSharedMemorySize, AT_SM);

    cvt_all<<<576, 256>>>((const float*)d_in[4], (const float*)d_in[6],
                          (const float*)d_in[10], (const float*)d_in[12]);
    gemm192_kernel<6, 0><<<1568, 256, G192_SM>>>(x, ln1g, ln1b, bqkv);
    attn_core<<<4096, 256, AT_SM>>>(msk);
    gemm192_kernel<2, 1><<<1568, 256, G192_SM>>>(x, (const float*)0, (const float*)0, bproj);
    mlp_kernel<<<1568, 512, MLP_SM>>>(ln2g, ln2b, bfc1, bfc2, out);
}

// round 17
// speedup vs baseline: 1.0278x; 1.0278x over previous
#include <cuda_runtime.h>
#include <cuda_bf16.h>
#include <mma.h>
#include <math.h>
#include <cstdint>

using namespace nvcuda;
typedef __nv_bfloat16 bf16;

#define LN_EPS 1e-5f

// persistent scratch (device globals: allocation-free)
__device__ float g_xres[(size_t)200704 * 192];        // mid residual
__device__ bf16  g_qkv [(size_t)200704 * 576];        // LN1 @ Wqkv^T + b
__device__ bf16  g_attno[(size_t)200704 * 192];       // attention output (pre-proj)
__device__ bf16  g_wqkv[576 * 192];
__device__ bf16  g_wproj[192 * 192];
__device__ bf16  g_wfc1[768 * 192];
__device__ bf16  g_wfc2[192 * 768];

typedef wmma::fragment<wmma::matrix_a, 16, 16, 16, bf16, wmma::row_major> FA;
typedef wmma::fragment<wmma::matrix_b, 16, 16, 16, bf16, wmma::col_major> FBc;
typedef wmma::fragment<wmma::matrix_b, 16, 16, 16, bf16, wmma::row_major> FBr;
typedef wmma::fragment<wmma::accumulator, 16, 16, 16, float> FC;

// ---------------------------------------------------------------------------
__device__ __forceinline__ void cpa16(void* smem_dst, const void* gsrc) {
    unsigned int a = (unsigned int)__cvta_generic_to_shared(smem_dst);
    asm volatile("cp.async.cg.shared.global [%0], [%1], 16;\n" :: "r"(a), "l"(gsrc));
}
#define CP_COMMIT() asm volatile("cp.async.commit_group;\n" ::: "memory")
#define CP_WAIT0()  asm volatile("cp.async.wait_group 0;\n" ::: "memory")

// ---------------------------------------------------------------------------
__global__ void cvt_all(const float* __restrict__ wqkv, const float* __restrict__ wproj,
                        const float* __restrict__ wfc1, const float* __restrict__ wfc2)
{
    int i = blockIdx.x * 256 + threadIdx.x;
    if (i < 110592) g_wqkv[i]  = __float2bfloat16(wqkv[i]);
    if (i < 36864)  g_wproj[i] = __float2bfloat16(wproj[i]);
    if (i < 147456) {
        g_wfc1[i] = __float2bfloat16(wfc1[i]);
        g_wfc2[i] = __float2bfloat16(wfc2[i]);
    }
}

// ---------------------------------------------------------------------------
// shared helpers
// ---------------------------------------------------------------------------
#define G192_SM (51200 + 2 * 19968 + 13312)

template <int NTHREADS>
__device__ __forceinline__ void stage_A_ln_t(bf16* As, const float* __restrict__ xr,
                                             const float* __restrict__ g,
                                             const float* __restrict__ b,
                                             int wid, int lane)
{
    for (int r = wid; r < 128; r += NTHREADS / 32) {
        float v[6]; float s = 0.f;
#pragma unroll
        for (int j = 0; j < 6; j++) { v[j] = xr[r * 192 + j * 32 + lane]; s += v[j]; }
#pragma unroll
        for (int o = 16; o; o >>= 1) s += __shfl_xor_sync(0xffffffffu, s, o);
        float mu = s * (1.f / 192.f);
        float va = 0.f;
#pragma unroll
        for (int j = 0; j < 6; j++) { float d = v[j] - mu; va += d * d; }
#pragma unroll
        for (int o = 16; o; o >>= 1) va += __shfl_xor_sync(0xffffffffu, va, o);
        float rstd = rsqrtf(va * (1.f / 192.f) + LN_EPS);
#pragma unroll
        for (int j = 0; j < 6; j++) {
            int c = j * 32 + lane;
            As[r * 200 + c] = __float2bfloat16((v[j] - mu) * rstd * g[c] + b[c]);
        }
    }
}

// async-copy one 96x96 B tile (256-thread)
__device__ __forceinline__ void copy_B_tile(bf16* Bs, const bf16* __restrict__ W,
                                            int ldw, int n0, int k0, int tid)
{
    const bf16* src = W + (size_t)n0 * ldw + k0;
    for (int idx = tid; idx < 96 * 12; idx += 256) {
        int r = idx / 12, ch = (idx - r * 12) * 8;
        cpa16(Bs + r * 104 + ch, src + (size_t)r * ldw + ch);
    }
}

// generic async tile copy: ROWS x (CH16*8 cols), NTHREADS threads, dst ld LDD
template <int ROWS, int CH16, int NTHREADS, int LDD>
__device__ __forceinline__ void copy_tile(bf16* dst, const bf16* __restrict__ src,
                                          int lds, int tid)
{
    for (int idx = tid; idx < ROWS * CH16; idx += NTHREADS) {
        int r = idx / CH16, ch = (idx - r * CH16) * 8;
        cpa16(dst + r * LDD + ch, src + (size_t)r * lds + ch);
    }
}

// mma over one 96-K chunk (warp tile 32x48, B ld 104)
__device__ __forceinline__ void mma_chunk(const bf16* As, int ldA, int kbase,
                                          const bf16* Bs, int mt, int ng, FC acc[6])
{
#pragma unroll
    for (int kk = 0; kk < 96; kk += 16) {
        FA a0, a1;
        wmma::load_matrix_sync(a0, As + (mt * 32) * ldA + kbase + kk, ldA);
        wmma::load_matrix_sync(a1, As + (mt * 32 + 16) * ldA + kbase + kk, ldA);
#pragma unroll
        for (int j = 0; j < 3; j++) {
            FBc b;
            wmma::load_matrix_sync(b, Bs + (ng * 48 + j * 16) * 104 + kk, 104);
            wmma::mma_sync(acc[j],     a0, b, acc[j]);
            wmma::mma_sync(acc[j + 3], a1, b, acc[j + 3]);
        }
    }
}

// ---------------------------------------------------------------------------
// Per-warp barrier-free epilogue (qkv)
// ---------------------------------------------------------------------------
__device__ __forceinline__ void epi_frags_qkv(float* ws, FC acc[6], int mt, int ng,
                                              int cbase, int row0,
                                              const float* __restrict__ bias, int lane)
{
#pragma unroll
    for (int j = 0; j < 6; j++) {
        int r0 = row0 + mt * 32 + (j >= 3 ? 16 : 0);
        int c0 = cbase + ng * 48 + (j % 3) * 16;
        wmma::store_matrix_sync(ws, acc[j], 20, wmma::mem_row_major);
        __syncwarp();
        int rr = lane >> 1, cc = (lane & 1) * 8;
        const float* sp = ws + rr * 20 + cc;
        int gr = r0 + rr, gc = c0 + cc;
        uint4 u; bf16* pb = (bf16*)&u;
#pragma unroll
        for (int q = 0; q < 8; q++) pb[q] = __float2bfloat16(sp[q] + bias[gc + q]);
        *(uint4*)(g_qkv + (size_t)gr * 576 + gc) = u;
        __syncwarp();
    }
}

// ---------------------------------------------------------------------------
// Coalesced block-staged epilogue for proj: +b + x -> g_xres
// ---------------------------------------------------------------------------
__device__ __forceinline__ void epi_slice_proj(float* buf, FC acc[6], int mt, int ng,
                                               int cbase, int row0,
                                               const float* __restrict__ xin,
                                               const float* __restrict__ bias, int tid)
{
#pragma unroll
    for (int ph = 0; ph < 4; ph++) {
        const int h = ph >> 1, c = ph & 1;
        __syncthreads();
        if ((mt >> 1) == h && ng == c) {
            int lr = (mt & 1) * 32;
#pragma unroll
            for (int j = 0; j < 3; j++) {
                wmma::store_matrix_sync(buf + lr * 52 + j * 16,        acc[j],     52, wmma::mem_row_major);
                wmma::store_matrix_sync(buf + (lr + 16) * 52 + j * 16, acc[j + 3], 52, wmma::mem_row_major);
            }
        }
        __syncthreads();
        for (int idx = tid; idx < 64 * 48; idx += 256) {
            int r = idx / 48, cc = idx - r * 48;
            int gr = row0 + h * 64 + r;
            int gc = cbase + c * 48 + cc;
            size_t gi = (size_t)gr * 192 + gc;
            g_xres[gi] = buf[r * 52 + cc] + bias[gc] + xin[gi];
        }
    }
}

// ---------------------------------------------------------------------------
// Unified K=192 GEMM (qkv OP0, proj OP1): block 256, CTA = 128 rows,
// cp.async-pipelined 96x96 B tiles.
// ---------------------------------------------------------------------------
template <int NSLICES, int OP>
__global__ __launch_bounds__(256) void gemm192_kernel(
    const float* __restrict__ xin, const float* __restrict__ lng,
    const float* __restrict__ lnb, const float* __restrict__ bias)
{
    extern __shared__ char smc[];
    bf16*  As   = (bf16*)smc;
    bf16*  Bb0  = (bf16*)(smc + 51200);
    bf16*  Bb1  = (bf16*)(smc + 51200 + 19968);
    float* epi  = (float*)(smc + 51200 + 2 * 19968);

    const bf16* W = (OP == 0) ? g_wqkv : g_wproj;

    const int tid = threadIdx.x, wid = tid >> 5, lane = tid & 31;
    const int row0 = blockIdx.x * 128;
    const int mt = wid & 3, ng = wid >> 2;
    float* ws = epi + wid * 320;

    copy_B_tile(Bb0, W, 192, 0, 0, tid);
    if (OP == 1) {
        const bf16* src = g_attno + (size_t)row0 * 192;
        for (int idx = tid; idx < 128 * 24; idx += 256) {
            int r = idx / 24, ch = (idx - r * 24) * 8;
            cpa16(As + r * 200 + ch, src + (size_t)r * 192 + ch);
        }
    }
    CP_COMMIT();

    if (OP == 0) stage_A_ln_t<256>(As, xin + (size_t)row0 * 192, lng, lnb, wid, lane);

    FC acc[6];
#pragma unroll
    for (int j = 0; j < 6; j++) wmma::fill_fragment(acc[j], 0.f);

    const int T = NSLICES * 2;
    for (int t = 0; t < T; t++) {
        const int s = t >> 1, c = t & 1;
        bf16* Bcur = (t & 1) ? Bb1 : Bb0;
        bf16* Bnxt = (t & 1) ? Bb0 : Bb1;
        CP_WAIT0();
        __syncthreads();
        if (t + 1 < T) {
            copy_B_tile(Bnxt, W, 192, ((t + 1) >> 1) * 96, ((t + 1) & 1) * 96, tid);
            CP_COMMIT();
        }
        mma_chunk(As, 200, c * 96, Bcur, mt, ng, acc);
        if (c == 1) {
            if (OP == 1)
                epi_slice_proj(epi, acc, mt, ng, s * 96, row0, xin, bias, tid);
            else
                epi_frags_qkv(ws, acc, mt, ng, s * 96, row0, bias, lane);
#pragma unroll
            for (int j = 0; j < 6; j++) wmma::fill_fragment(acc[j], 0.f);
        }
    }
}

// ---------------------------------------------------------------------------
// FUSED MLP v1 (reverted: measured best): block 512 (16 warps), CTA = 128
// rows. 8 hid-chunks of 96: fc1 (warp 16x48) -> bias+GELU -> hb smem bf16 ->
// fc2 partial (warp 32x48, persistent acc) -> epilogue +bfc2 +xres.
// smem: xn 51200 | W1b 38400 | W2b 39936 | hb 26624 | ws/buf 20480 = 176640
// ---------------------------------------------------------------------------
#define MLP_SM (51200 + 38400 + 39936 + 26624 + 20480)

__global__ __launch_bounds__(512) void mlp_kernel(
    const float* __restrict__ ln2g, const float* __restrict__ ln2b,
    const float* __restrict__ bfc1, const float* __restrict__ bfc2,
    float* __restrict__ out)
{
    extern __shared__ char smc[];
    bf16*  xn  = (bf16*)smc;                       // 128x200
    bf16*  W1b = (bf16*)(smc + 51200);             // 96x200
    bf16*  W2b = (bf16*)(smc + 51200 + 38400);     // 192x104
    bf16*  hb  = (bf16*)(smc + 51200 + 38400 + 39936);  // 128x104
    float* wsb = (float*)(smc + 51200 + 38400 + 39936 + 26624);

    const int tid = threadIdx.x, wid = tid >> 5, lane = tid & 31;
    const int row0 = blockIdx.x * 128;
    const int r16 = wid & 7, c2 = wid >> 3;        // fc1 tiling 16x48
    const int mtf = wid & 3, ngf = wid >> 2;       // fc2 tiling 32x48
    float* ws = wsb + wid * 320;

    copy_tile<96, 24, 512, 200>(W1b, g_wfc1, 192, tid);
    copy_tile<192, 12, 512, 104>(W2b, g_wfc2, 768, tid);
    CP_COMMIT();

    stage_A_ln_t<512>(xn, g_xres + (size_t)row0 * 192, ln2g, ln2b, wid, lane);

    FC acc[6];
#pragma unroll
    for (int j = 0; j < 6; j++) wmma::fill_fragment(acc[j], 0.f);

    for (int p = 0; p < 8; p++) {
        CP_WAIT0();
        __syncthreads();

        FC f[3];
#pragma unroll
        for (int j = 0; j < 3; j++) wmma::fill_fragment(f[j], 0.f);
#pragma unroll
        for (int k0 = 0; k0 < 192; k0 += 16) {
            FA a;
            wmma::load_matrix_sync(a, xn + (r16 * 16) * 200 + k0, 200);
#pragma unroll
            for (int j = 0; j < 3; j++) {
                FBc b;
                wmma::load_matrix_sync(b, W1b + (c2 * 48 + j * 16) * 200 + k0, 200);
                wmma::mma_sync(f[j], a, b, f[j]);
            }
        }
#pragma unroll
        for (int j = 0; j < 3; j++) {
            wmma::store_matrix_sync(ws, f[j], 20, wmma::mem_row_major);
            __syncwarp();
            int rr = lane >> 1, cc = (lane & 1) * 8;
            const float* sp = ws + rr * 20 + cc;
            int lr = r16 * 16 + rr;
            int lc = c2 * 48 + j * 16 + cc;
            uint4 u; bf16* pb = (bf16*)&u;
#pragma unroll
            for (int q = 0; q < 8; q++) {
                float v = sp[q] + bfc1[p * 96 + lc + q];
                v = 0.5f * v * (1.f + erff(v * 0.70710678118654752f));
                pb[q] = __float2bfloat16(v);
            }
            *(uint4*)(hb + lr * 104 + lc) = u;
            __syncwarp();
        }
        __syncthreads();

        if (p + 1 < 8)
            copy_tile<96, 24, 512, 200>(W1b, g_wfc1 + (size_t)(p + 1) * 96 * 192, 192, tid);

        mma_chunk(hb, 104, 0, W2b, mtf, ngf, acc);
        __syncthreads();

        if (p + 1 < 8) {
            copy_tile<192, 12, 512, 104>(W2b, g_wfc2 + (size_t)(p + 1) * 96, 768, tid);
            CP_COMMIT();
        }
    }

    float* buf = wsb;
#pragma unroll
    for (int h = 0; h < 2; h++)
#pragma unroll
        for (int c = 0; c < 4; c++) {
            __syncthreads();
            if ((mtf >> 1) == h && ngf == c) {
                int lr = (mtf & 1) * 32;
#pragma unroll
                for (int j = 0; j < 3; j++) {
                    wmma::store_matrix_sync(buf + lr * 52 + j * 16,        acc[j],     52, wmma::mem_row_major);
                    wmma::store_matrix_sync(buf + (lr + 16) * 52 + j * 16, acc[j + 3], 52, wmma::mem_row_major);
                }
            }
            __syncthreads();
            for (int idx = tid; idx < 64 * 48; idx += 512) {
                int r = idx / 48, cc = idx - r * 48;
                int gr = row0 + h * 64 + r;
                int gc = c * 48 + cc;
                size_t gi = (size_t)gr * 192 + gc;
                out[gi] = buf[r * 52 + cc] + bfc2[gc] + g_xres[gi];
            }
        }
}

// ---------------------------------------------------------------------------
// attention core v3: ONE CTA PER WINDOW, 6 heads, cp.async double-buffered
// q/k/v head slices; mask as bitmasks; 3 barriers/head (PV output copied
// per-warp from the warp's own pvbuf region — no block barrier needed; the
// next head's CP_WAIT+sync orders pvbuf reuse).  smem 57856 -> 3 CTAs/SM
// ---------------------------------------------------------------------------
#define AT_SM (2 * 15360 + 17408 + 9216 + 512)

__device__ __forceinline__ void stage_qkv_head(bf16* dst, size_t base, int h, int tid)
{
    for (int idx = tid; idx < 588; idx += 256) {
        int m = idx / 196, rem = idx - m * 196;
        int r = rem >> 2, c8 = (rem & 3) * 8;
        cpa16(dst + m * 2560 + r * 40 + c8,
              g_qkv + base + (size_t)r * 576 + m * 192 + h * 32 + c8);
    }
}

__global__ __launch_bounds__(256) void attn_core(const int* __restrict__ mask)
{
    extern __shared__ char smc[];
    bf16*  qkvb0 = (bf16*)smc;
    bf16*  qkvb1 = (bf16*)(smc + 15360);
    float* S     = (float*)(smc + 30720);
    bf16*  P     = (bf16*)(smc + 48128);
    unsigned long long* mb = (unsigned long long*)(smc + 57344);
    float* pvbuf = S;

    const int tid = threadIdx.x, wid = tid >> 5, lane = tid & 31;
    const int win = blockIdx.x;
    const size_t base = (size_t)(win * 49) * 576;

    {
        const int* mrow_base = mask + (size_t)win * 49 * 49;
        for (int r = wid; r < 49; r += 8) {
            const int* mrow = mrow_base + r * 49;
            unsigned m1 = __ballot_sync(0xffffffffu, mrow[lane] != 0);
            unsigned m2 = __ballot_sync(0xffffffffu,
                                        (lane + 32 < 49) ? (mrow[lane + 32] != 0) : 0);
            if (lane == 0) mb[r] = ((unsigned long long)m2 << 32) | m1;
        }
    }
    for (int idx = tid; idx < 150; idx += 256) {
        int b = idx / 75, e = idx - b * 75;
        int r = 49 + e / 5, c8 = (e % 5) * 8;
        bf16* vdst = (b ? qkvb1 : qkvb0) + 5120 + r * 40 + c8;
        uint4 z; z.x = z.y = z.z = z.w = 0u;
        *(uint4*)vdst = z;
    }

    stage_qkv_head(qkvb0, base, 0, tid);
    CP_COMMIT();
    __syncthreads();

    for (int h = 0; h < 6; h++) {
        bf16* cur = (h & 1) ? qkvb1 : qkvb0;
        bf16* nxt = (h & 1) ? qkvb0 : qkvb1;
        CP_WAIT0();
        __syncthreads();                       // barrier 1: buffers + pvbuf reuse
        if (h + 1 < 6) {
            stage_qkv_head(nxt, base, h + 1, tid);
            CP_COMMIT();
        }
        bf16* qs = cur, *ks = cur + 2560, *vs = cur + 5120;

#pragma unroll
        for (int it = 0; it < 2; it++) {
            int t = wid + it * 8;
            int mt = t & 3, nt = t >> 2;
            FC c;
            wmma::fill_fragment(c, 0.f);
#pragma unroll
            for (int k0 = 0; k0 < 32; k0 += 16) {
                FA a;
                wmma::load_matrix_sync(a, qs + mt * 16 * 40 + k0, 40);
                FBc b;
                wmma::load_matrix_sync(b, ks + nt * 16 * 40 + k0, 40);
                wmma::mma_sync(c, a, b, c);
            }
            wmma::store_matrix_sync(S + mt * 16 * 68 + nt * 16, c, 68, wmma::mem_row_major);
        }
        __syncthreads();                       // barrier 2: S complete

        {
            const float scale = 0.17677669529663687f;
            for (int r = wid; r < 49; r += 8) {
                unsigned long long bits = mb[r];
                int j2 = lane + 32;
                bool m1 = (bits >> lane) & 1ull;
                bool m2 = (j2 < 49) && ((bits >> j2) & 1ull);
                float s1 = m1 ? S[r * 68 + lane] * scale : -1e30f;
                float s2 = m2 ? S[r * 68 + j2] * scale : -1e30f;
                float m = fmaxf(s1, s2);
#pragma unroll
                for (int o = 16; o; o >>= 1) m = fmaxf(m, __shfl_xor_sync(0xffffffffu, m, o));
                float e1 = __expf(s1 - m);
                float e2 = (j2 < 49) ? __expf(s2 - m) : 0.f;
                float sum = e1 + e2;
#pragma unroll
                for (int o = 16; o; o >>= 1) sum += __shfl_xor_sync(0xffffffffu, sum, o);
                float inv = 1.f / sum;
                P[r * 72 + lane] = __float2bfloat16(e1 * inv);
                P[r * 72 + j2]   = __float2bfloat16(e2 * inv);
            }
        }
        __syncthreads();                       // barrier 3: P complete

        // PV + per-warp output copy (no block barriers)
        {
            int mt = wid & 3, nt = wid >> 2;
            FC c;
            wmma::fill_fragment(c, 0.f);
#pragma unroll
            for (int k0 = 0; k0 < 64; k0 += 16) {
                FA a;
                wmma::load_matrix_sync(a, P + mt * 16 * 72 + k0, 72);
                FBr b;
                wmma::load_matrix_sync(b, vs + k0 * 40 + nt * 16, 40);
                wmma::mma_sync(c, a, b, c);
            }
            float* wpv = pvbuf + mt * 16 * 40 + nt * 16;   // own 16x16 region
            wmma::store_matrix_sync(wpv, c, 40, wmma::mem_row_major);
            __syncwarp();
            int rr = lane >> 1, cc = (lane & 1) * 8;
            int gr = mt * 16 + rr;
            if (gr < 49) {
                const float* sp = wpv + rr * 40 + cc;
                uint4 u; bf16* pb = (bf16*)&u;
#pragma unroll
                for (int q = 0; q < 8; q++) pb[q] = __float2bfloat16(sp[q]);
                *(uint4*)(g_attno + (size_t)(win * 49 + gr) * 192 + h * 32 + nt * 16 + cc) = u;
            }
            __syncwarp();
        }
        // no trailing barrier: next head's CP_WAIT+sync orders pvbuf reuse
    }
}

// ---------------------------------------------------------------------------

extern "C" void kernel_launch(void* const* d_in, const int* in_sizes, int n_in,
                              void* d_out, int out_size)
{
    const float* x     = (const float*)d_in[0];
    const int*   msk   = (const int*)  d_in[1];
    const float* ln1g  = (const float*)d_in[2];
    const float* ln1b  = (const float*)d_in[3];
    const float* bqkv  = (const float*)d_in[5];
    const float* bproj = (const float*)d_in[7];
    const float* ln2g  = (const float*)d_in[8];
    const float* ln2b  = (const float*)d_in[9];
    const float* bfc1  = (const float*)d_in[11];
    const float* bfc2  = (const float*)d_in[13];
    float* out = (float*)d_out;

    cudaFuncSetAttribute(gemm192_kernel<6, 0>, cudaFuncAttributeMaxDynamicSharedMemorySize, G192_SM);
    cudaFuncSetAttribute(gemm192_kernel<2, 1>, cudaFuncAttributeMaxDynamicSharedMemorySize, G192_SM);
    cudaFuncSetAttribute(mlp_kernel, cudaFuncAttributeMaxDynamicSharedMemorySize, MLP_SM);
    cudaFuncSetAttribute(attn_core,  cudaFuncAttributeMaxDynamicSharedMemorySize, AT_SM);

    cvt_all<<<576, 256>>>((const float*)d_in[4], (const float*)d_in[6],
                          (const float*)d_in[10], (const float*)d_in[12]);
    gemm192_kernel<6, 0><<<1568, 256, G192_SM>>>(x, ln1g, ln1b, bqkv);
    attn_core<<<4096, 256, AT_SM>>>(msk);
    gemm192_kernel<2, 1><<<1568, 256, G192_SM>>>(x, (const float*)0, (const float*)0, bproj);
    mlp_kernel<<<1568, 512, MLP_SM>>>(ln2g, ln2b, bfc1, bfc2, out);
}